// round 4
// baseline (speedup 1.0000x reference)
#include <cuda_runtime.h>
#include <cstdint>

#define N_TOK   4096
#define C_DIM   64
#define HW      256
#define E_EXP   16
#define CCAP    384
#define PLANE   (E_EXP * CCAP)             /* 6144 */
#define HALF    ((long long)N_TOK * PLANE) /* 25,165,824 floats */
#define ZCHUNK  3072                        /* float4 of zeros per block: 2*HALF/4/4096 */

// ---------------- device scratch (reset each run by finish block) ----------------
__device__ float g_gate[N_TOK];
__device__ int   g_arg[N_TOK];
__device__ float g_psum[E_EXP];
__device__ float g_zsum;
__device__ int   g_ctr;

// =====================================================================
// Single kernel, uniform work blocks. grid = 4097 x 512.
//   bid < 4096 : pool token bid (64KB read) + zero 48KB output slice
//   bid == 4096: finish (wait, scan, scatter, scalars, state reset)
// =====================================================================
__global__ void __launch_bounds__(512)
k_all(const float* __restrict__ X, const float* __restrict__ Wg,
      const float* __restrict__ bg, float* __restrict__ out) {
    const int bid  = blockIdx.x;
    const int tid  = threadIdx.x;
    const int w    = tid >> 5;
    const int lane = tid & 31;

    if (bid < N_TOK) {
        const int n = bid;
        __shared__ float s_ch[C_DIM];
        __shared__ float s_w[C_DIM * E_EXP];

        // issue the 8 X loads first (streaming policy, MLP=8)
        const float4* p = reinterpret_cast<const float4*>(X + (size_t)n * C_DIM * HW)
                          + w * 256;                 // warp w owns channels [4w,4w+4)
        float4 v0 = __ldcs(p + lane +   0);
        float4 v1 = __ldcs(p + lane +  32);
        float4 v2 = __ldcs(p + lane +  64);
        float4 v3 = __ldcs(p + lane +  96);
        float4 v4 = __ldcs(p + lane + 128);
        float4 v5 = __ldcs(p + lane + 160);
        float4 v6 = __ldcs(p + lane + 192);
        float4 v7 = __ldcs(p + lane + 224);

        // zero this block's output slice while loads are in flight
        {
            float4* o4 = reinterpret_cast<float4*>(out) + (size_t)n * ZCHUNK;
            const float4 zv = make_float4(0.f, 0.f, 0.f, 0.f);
#pragma unroll
            for (int i = 0; i < 6; i++) __stcs(o4 + i * 512 + tid, zv);
        }

        // stage W_gate (L2-resident, reused by all blocks)
        for (int i = tid; i < C_DIM * E_EXP; i += 512) s_w[i] = Wg[i];

        // channel partial sums
        float part[4];
        part[0] = (v0.x + v0.y + v0.z + v0.w) + (v1.x + v1.y + v1.z + v1.w);
        part[1] = (v2.x + v2.y + v2.z + v2.w) + (v3.x + v3.y + v3.z + v3.w);
        part[2] = (v4.x + v4.y + v4.z + v4.w) + (v5.x + v5.y + v5.z + v5.w);
        part[3] = (v6.x + v6.y + v6.z + v6.w) + (v7.x + v7.y + v7.z + v7.w);
#pragma unroll
        for (int c = 0; c < 4; c++) {
            float s = part[c];
#pragma unroll
            for (int off = 16; off; off >>= 1) s += __shfl_xor_sync(0xffffffffu, s, off);
            if (lane == 0) s_ch[4 * w + c] = s * (1.0f / HW);
        }
        __syncthreads();

        if (w == 0) {
            float l = -INFINITY;
            if (lane < E_EXP) {
                float acc = bg[lane];
#pragma unroll
                for (int c = 0; c < C_DIM; c++) acc += s_ch[c] * s_w[c * E_EXP + lane];
                l = acc;
            }
            float mx = l;
#pragma unroll
            for (int off = 16; off; off >>= 1) mx = fmaxf(mx, __shfl_xor_sync(0xffffffffu, mx, off));
            float e = (lane < E_EXP) ? __expf(l - mx) : 0.f;
            float s = e;
#pragma unroll
            for (int off = 16; off; off >>= 1) s += __shfl_xor_sync(0xffffffffu, s, off);
            float prob = e / s;
            float lse  = mx + __logf(s);

            unsigned bal = __ballot_sync(0xffffffffu, l == mx);
            int arg = __ffs(bal) - 1;                // lowest-index max == jnp argmax
            float gate = __shfl_sync(0xffffffffu, prob, arg);

            if (lane < E_EXP) atomicAdd(&g_psum[lane], prob);
            if (lane == 0) { g_gate[n] = gate; g_arg[n] = arg; atomicAdd(&g_zsum, lse); }
        }
        // all zero-stores + scratch writes done -> signal
        __syncthreads();
        if (tid == 0) { __threadfence(); atomicAdd(&g_ctr, 1); }
        return;
    }

    // ---------------- finish block (bid == 4096) ----------------
    __shared__ unsigned short s_rank[N_TOK];
    __shared__ unsigned char  s_argc[N_TOK];
    __shared__ int s_cnt[16][E_EXP + 1];
    __shared__ int s_off[16][E_EXP + 1];
    __shared__ int s_tot[E_EXP];

    if (tid == 0) {
        while (atomicAdd(&g_ctr, 0) < N_TOK) __nanosleep(64);
        __threadfence();
    }
    __syncthreads();

    // phase A: per-chunk expert ranks (warp w owns tokens [256w, 256w+256))
    if (lane <= E_EXP) s_cnt[w][lane] = 0;
    __syncwarp();
#pragma unroll
    for (int g = 0; g < 8; g++) {
        int n = 256 * w + 32 * g + lane;
        int a = g_arg[n];
        unsigned m = __match_any_sync(0xffffffffu, a);
        int prior = s_cnt[w][a];
        __syncwarp();
        if (lane == (int)__ffs(m) - 1) s_cnt[w][a] = prior + __popc(m);
        s_rank[n] = (unsigned short)(prior + __popc(m & ((1u << lane) - 1u)));
        s_argc[n] = (unsigned char)a;
        __syncwarp();
    }
    __syncthreads();

    // phase B: exclusive prefix over 16 chunks (warp w<16 = expert w)
    if (w < E_EXP && lane < 16) {
        int v = s_cnt[lane][w];
        int x = v;
#pragma unroll
        for (int off = 1; off < 16; off <<= 1) {
            int y = __shfl_up_sync(0x0000ffffu, x, off);
            if (lane >= off) x += y;
        }
        s_off[lane][w] = x - v;
        if (lane == 15) s_tot[w] = x;
    }
    __syncthreads();

    // phase C: positions + scatter nonzeros
#pragma unroll
    for (int rep = 0; rep < 8; rep++) {
        int n = tid + rep * 512;
        int a = s_argc[n];
        int pos = s_off[n >> 8][a] + (int)s_rank[n];
        if (pos < CCAP) {
            long long off = (long long)n * PLANE + a * CCAP + pos;
            __stcs(out + off, 1.0f);             // dispatch
            __stcs(out + HALF + off, g_gate[n]); // combine
        }
    }

    // scalars + state reset for next graph replay
    if (tid == 0) {
        float aux = 0.f;
#pragma unroll
        for (int e = 0; e < E_EXP; e++) aux += g_psum[e] * (float)s_tot[e];
        const float invN = 1.0f / (float)N_TOK;
        out[2 * HALF]     = g_zsum * invN;                       // z_loss
        out[2 * HALF + 1] = aux * (float)E_EXP * invN * invN;    // aux_loss
        g_zsum = 0.f;
#pragma unroll
        for (int e = 0; e < E_EXP; e++) g_psum[e] = 0.f;
        __threadfence();
        g_ctr = 0;
    }
}

// ---------------- launch ----------------
extern "C" void kernel_launch(void* const* d_in, const int* in_sizes, int n_in,
                              void* d_out, int out_size) {
    const float* X  = (const float*)d_in[0];
    const float* Wg = (const float*)d_in[1];
    const float* bg = (const float*)d_in[2];
    float* out = (float*)d_out;

    k_all<<<N_TOK + 1, 512>>>(X, Wg, bg, out);
}

// round 5
// speedup vs baseline: 1.0460x; 1.0460x over previous
#include <cuda_runtime.h>
#include <cstdint>

#define N_TOK   4096
#define C_DIM   64
#define HW      256
#define E_EXP   16
#define CCAP    384
#define PLANE   (E_EXP * CCAP)             /* 6144 */
#define HALF    ((long long)N_TOK * PLANE) /* 25,165,824 floats */
#define NZERO   3072                        /* zero blocks, 4096 float4 each */
#define NWORK   (N_TOK + NZERO)             /* 7168 */

// ---------------- device scratch (reset each run by finish block) ----------------
__device__ float g_gate[N_TOK];
__device__ int   g_arg[N_TOK];
__device__ float g_psum[E_EXP];
__device__ float g_zsum;
__device__ int   g_ctr;

// =====================================================================
// Single kernel. grid = 7169 x 512.
//   Groups of 7 bids: first 3 -> zero blocks (64KB writes each),
//                     next 4  -> pool blocks (64KB reads each).
//   bid == 7168 -> finish block (wait, scan, scatter, scalars, reset).
// =====================================================================
__global__ void __launch_bounds__(512, 4)
k_all(const float* __restrict__ X, const float* __restrict__ Wg,
      const float* __restrict__ bg, float* __restrict__ out) {
    const int bid  = blockIdx.x;
    const int tid  = threadIdx.x;
    const int w    = tid >> 5;
    const int lane = tid & 31;

    if (bid < NWORK) {
        const int grp = bid / 7;
        const int sub = bid % 7;

        if (sub < 3) {
            // ---------------- zero block: zid in [0, 3072) ----------------
            const long long zid = (long long)grp * 3 + sub;
            float4* o4 = reinterpret_cast<float4*>(out) + zid * 4096;
            const float4 zv = make_float4(0.f, 0.f, 0.f, 0.f);
#pragma unroll
            for (int i = 0; i < 8; i++) __stcs(o4 + i * 512 + tid, zv);
            __syncthreads();
            if (tid == 0) { __threadfence(); atomicAdd(&g_ctr, 1); }
            return;
        }

        // ---------------- pool block: token n in [0, 4096) ----------------
        const int n = grp * 4 + (sub - 3);

        __shared__ float s_ch[C_DIM];
        __shared__ float s_w[C_DIM * E_EXP];

        for (int i = tid; i < C_DIM * E_EXP; i += 512) s_w[i] = Wg[i];

        // coalesced streaming read: warp w owns channels [4w, 4w+4)
        const float4* p = reinterpret_cast<const float4*>(X + (size_t)n * C_DIM * HW)
                          + w * 256;
        float part[4] = {0.f, 0.f, 0.f, 0.f};
#pragma unroll
        for (int k = 0; k < 8; k++) {
            float4 v = __ldcs(p + lane + 32 * k);   // lanes consecutive -> coalesced
            part[k >> 1] += (v.x + v.y) + (v.z + v.w);
        }
#pragma unroll
        for (int c = 0; c < 4; c++) {
            float s = part[c];
#pragma unroll
            for (int off = 16; off; off >>= 1) s += __shfl_xor_sync(0xffffffffu, s, off);
            if (lane == 0) s_ch[4 * w + c] = s * (1.0f / HW);
        }
        __syncthreads();

        if (w == 0) {
            float l = -INFINITY;
            if (lane < E_EXP) {
                float acc = bg[lane];
#pragma unroll
                for (int c = 0; c < C_DIM; c++) acc += s_ch[c] * s_w[c * E_EXP + lane];
                l = acc;
            }
            float mx = l;
#pragma unroll
            for (int off = 16; off; off >>= 1) mx = fmaxf(mx, __shfl_xor_sync(0xffffffffu, mx, off));
            float e = (lane < E_EXP) ? __expf(l - mx) : 0.f;
            float s = e;
#pragma unroll
            for (int off = 16; off; off >>= 1) s += __shfl_xor_sync(0xffffffffu, s, off);
            float prob = e / s;
            float lse  = mx + __logf(s);

            unsigned bal = __ballot_sync(0xffffffffu, l == mx);
            int arg = __ffs(bal) - 1;               // lowest-index max == jnp argmax
            float gate = __shfl_sync(0xffffffffu, prob, arg);

            if (lane < E_EXP) atomicAdd(&g_psum[lane], prob);
            if (lane == 0) {
                g_gate[n] = gate;
                g_arg[n]  = arg;
                atomicAdd(&g_zsum, lse);
                __threadfence();
                atomicAdd(&g_ctr, 1);
            }
        }
        return;
    }

    // ---------------- finish block (bid == 7168) ----------------
    __shared__ unsigned short s_rank[N_TOK];
    __shared__ unsigned char  s_argc[N_TOK];
    __shared__ int s_cnt[16][E_EXP + 1];
    __shared__ int s_off[16][E_EXP + 1];
    __shared__ int s_tot[E_EXP];

    if (tid == 0) {
        while (atomicAdd(&g_ctr, 0) < NWORK) __nanosleep(64);
        __threadfence();
    }
    __syncthreads();

    // phase A: per-chunk expert ranks (warp w owns tokens [256w, 256w+256))
    if (lane <= E_EXP) s_cnt[w][lane] = 0;
    __syncwarp();
#pragma unroll
    for (int g = 0; g < 8; g++) {
        int n = 256 * w + 32 * g + lane;
        int a = g_arg[n];
        unsigned m = __match_any_sync(0xffffffffu, a);
        int prior = s_cnt[w][a];
        __syncwarp();
        if (lane == (int)__ffs(m) - 1) s_cnt[w][a] = prior + __popc(m);
        s_rank[n] = (unsigned short)(prior + __popc(m & ((1u << lane) - 1u)));
        s_argc[n] = (unsigned char)a;
        __syncwarp();
    }
    __syncthreads();

    // phase B: exclusive prefix over 16 chunks (warp w<16 = expert w)
    if (w < E_EXP && lane < 16) {
        int v = s_cnt[lane][w];
        int x = v;
#pragma unroll
        for (int off = 1; off < 16; off <<= 1) {
            int y = __shfl_up_sync(0x0000ffffu, x, off);
            if (lane >= off) x += y;
        }
        s_off[lane][w] = x - v;
        if (lane == 15) s_tot[w] = x;
    }
    __syncthreads();

    // phase C: positions + scatter nonzeros
#pragma unroll
    for (int rep = 0; rep < 8; rep++) {
        int n = tid + rep * 512;
        int a = s_argc[n];
        int pos = s_off[n >> 8][a] + (int)s_rank[n];
        if (pos < CCAP) {
            long long off = (long long)n * PLANE + a * CCAP + pos;
            __stcs(out + off, 1.0f);              // dispatch
            __stcs(out + HALF + off, g_gate[n]);  // combine
        }
    }

    // scalars + state reset for next graph replay
    if (tid == 0) {
        float aux = 0.f;
#pragma unroll
        for (int e = 0; e < E_EXP; e++) aux += g_psum[e] * (float)s_tot[e];
        const float invN = 1.0f / (float)N_TOK;
        out[2 * HALF]     = g_zsum * invN;                       // z_loss
        out[2 * HALF + 1] = aux * (float)E_EXP * invN * invN;    // aux_loss
        g_zsum = 0.f;
#pragma unroll
        for (int e = 0; e < E_EXP; e++) g_psum[e] = 0.f;
        __threadfence();
        g_ctr = 0;
    }
}

// ---------------- launch ----------------
extern "C" void kernel_launch(void* const* d_in, const int* in_sizes, int n_in,
                              void* d_out, int out_size) {
    const float* X  = (const float*)d_in[0];
    const float* Wg = (const float*)d_in[1];
    const float* bg = (const float*)d_in[2];
    float* out = (float*)d_out;

    k_all<<<NWORK + 1, 512>>>(X, Wg, bg, out);
}